// round 3
// baseline (speedup 1.0000x reference)
#include <cuda_runtime.h>
#include <cstdint>
#include <cstddef>

// Problem constants
#define T_STEPS 64
#define BATCH   256
#define NINF    1024
#define HDIM    2048
#define G4      8192   // 4*H
#define LN_EPS  1e-5f

// Scratch (device globals: allocation-free rule). R2 proved 512MB bss is fine.
__device__ float g_zx[(size_t)T_STEPS * BATCH * G4]; // LN(x@wx), all t (512 MB, fp32!)
__device__ float g_gw[(size_t)BATCH * G4];           // h@wh current step (8 MB)
__device__ float g_c[BATCH * HDIM];
__device__ float g_h[BATCH * HDIM];

// ---------------------------------------------------------------------------
// SGEMM: C[M,N] = (diag(scale) * A[M,K]) @ B[K,N], fp32, tiles 128x128x8.
// rowmask != nullptr -> scale[m] = 1 - rowmask[m]
// M % 128 == 0, N % 128 == 0, K % 8 == 0.
// ---------------------------------------------------------------------------
__global__ __launch_bounds__(256) void sgemm_kernel(
    const float* __restrict__ A, const float* __restrict__ B,
    float* __restrict__ C, int M, int N, int K,
    const float* __restrict__ rowmask)
{
    __shared__ float As[8][128];
    __shared__ float Bs[8][128];

    const int tid = threadIdx.x;
    const int bn = blockIdx.x, bm = blockIdx.y;

    const int arow = tid >> 1;          // 0..127
    const int acol = (tid & 1) << 2;    // 0 or 4
    const int brow = tid >> 5;          // 0..7
    const int bcol = (tid & 31) << 2;   // 0..124

    const float* Ap = A + (size_t)(bm * 128 + arow) * K + acol;
    const float* Bp = B + (size_t)brow * N + bn * 128 + bcol;

    float scale = 1.0f;
    if (rowmask) scale = 1.0f - rowmask[bm * 128 + arow];

    const int tx = tid & 15, ty = tid >> 4;

    float acc[8][8];
#pragma unroll
    for (int i = 0; i < 8; i++)
#pragma unroll
        for (int j = 0; j < 8; j++) acc[i][j] = 0.0f;

    for (int k0 = 0; k0 < K; k0 += 8) {
        float4 av = *(const float4*)(Ap + k0);
        float4 bv = *(const float4*)(Bp + (size_t)k0 * N);
        As[acol + 0][arow] = av.x * scale;
        As[acol + 1][arow] = av.y * scale;
        As[acol + 2][arow] = av.z * scale;
        As[acol + 3][arow] = av.w * scale;
        *(float4*)(&Bs[brow][bcol]) = bv;
        __syncthreads();

#pragma unroll
        for (int kk = 0; kk < 8; kk++) {
            float a[8], b[8];
            *(float4*)(a)     = *(const float4*)(&As[kk][ty * 8]);
            *(float4*)(a + 4) = *(const float4*)(&As[kk][ty * 8 + 4]);
            *(float4*)(b)     = *(const float4*)(&Bs[kk][tx * 8]);
            *(float4*)(b + 4) = *(const float4*)(&Bs[kk][tx * 8 + 4]);
#pragma unroll
            for (int i = 0; i < 8; i++)
#pragma unroll
                for (int j = 0; j < 8; j++)
                    acc[i][j] = fmaf(a[i], b[j], acc[i][j]);
        }
        __syncthreads();
    }

    float* Cp = C + (size_t)(bm * 128 + ty * 8) * N + bn * 128 + tx * 8;
#pragma unroll
    for (int i = 0; i < 8; i++) {
        *(float4*)(Cp + (size_t)i * N) =
            make_float4(acc[i][0], acc[i][1], acc[i][2], acc[i][3]);
        *(float4*)(Cp + (size_t)i * N + 4) =
            make_float4(acc[i][4], acc[i][5], acc[i][6], acc[i][7]);
    }
}

// ---------------------------------------------------------------------------
// Block reduction (256 threads)
// ---------------------------------------------------------------------------
__device__ __forceinline__ float block_reduce_sum(float v, float* sbuf)
{
#pragma unroll
    for (int o = 16; o > 0; o >>= 1) v += __shfl_down_sync(0xffffffffu, v, o);
    const int lane = threadIdx.x & 31, w = threadIdx.x >> 5;
    if (lane == 0) sbuf[w] = v;
    __syncthreads();
    if (w == 0) {
        v = (lane < 8) ? sbuf[lane] : 0.0f;
#pragma unroll
        for (int o = 16; o > 0; o >>= 1) v += __shfl_down_sync(0xffffffffu, v, o);
        if (lane == 0) sbuf[0] = v;
    }
    __syncthreads();
    v = sbuf[0];
    __syncthreads();
    return v;
}

// ---------------------------------------------------------------------------
// In-place row LayerNorm over width 8192 (for LN(x@wx)). 1 CTA / row.
// ---------------------------------------------------------------------------
__global__ __launch_bounds__(256) void ln_rows_kernel(
    float* __restrict__ Z, const float* __restrict__ g, const float* __restrict__ b)
{
    __shared__ float sbuf[32];
    const int tid = threadIdx.x;
    float* row = Z + (size_t)blockIdx.x * G4;

    float v[32];
    float s = 0.0f;
#pragma unroll
    for (int i = 0; i < 32; i++) { v[i] = row[tid + i * 256]; s += v[i]; }
    const float mean = block_reduce_sum(s, sbuf) * (1.0f / G4);

    float sq = 0.0f;
#pragma unroll
    for (int i = 0; i < 32; i++) { float d = v[i] - mean; sq += d * d; }
    const float var = block_reduce_sum(sq, sbuf) * (1.0f / G4);
    const float rstd = rsqrtf(var + LN_EPS);

#pragma unroll
    for (int i = 0; i < 32; i++) {
        const int col = tid + i * 256;
        row[col] = (v[i] - mean) * rstd * g[col] + b[col];
    }
}

// ---------------------------------------------------------------------------
// Per-step fused LSTM pointwise: LN(h@wh) + zx + b -> gates -> c,h update
// + LN(c) -> h_out.  1 CTA per batch row.
// ---------------------------------------------------------------------------
__global__ __launch_bounds__(256) void lstm_step_kernel(
    const float* __restrict__ gw, const float* __restrict__ zx_t,
    const float* __restrict__ mask_t, const float* __restrict__ bias,
    const float* __restrict__ gh, const float* __restrict__ bh,
    const float* __restrict__ gc, const float* __restrict__ bc,
    float* __restrict__ c_st, float* __restrict__ h_st,
    float* __restrict__ hs_out)
{
    __shared__ float zsh[G4];      // 32 KB
    __shared__ float sbuf[32];

    const int bb = blockIdx.x, tid = threadIdx.x;
    const float* grow = gw + (size_t)bb * G4;
    const float* zrow = zx_t + (size_t)bb * G4;

    // LN over the h@wh row
    float v[32];
    float s = 0.0f;
#pragma unroll
    for (int i = 0; i < 32; i++) { v[i] = grow[tid + i * 256]; s += v[i]; }
    const float mean = block_reduce_sum(s, sbuf) * (1.0f / G4);
    float sq = 0.0f;
#pragma unroll
    for (int i = 0; i < 32; i++) { float d = v[i] - mean; sq += d * d; }
    const float var = block_reduce_sum(sq, sbuf) * (1.0f / G4);
    const float rstd = rsqrtf(var + LN_EPS);

#pragma unroll
    for (int i = 0; i < 32; i++) {
        const int col = tid + i * 256;
        zsh[col] = zrow[col] + (v[i] - mean) * rstd * gh[col] + bh[col] + bias[col];
    }
    __syncthreads();

    // Gates + c update
    const float keep = 1.0f - mask_t[bb];
    float cv[8], ov[8];
    float s2 = 0.0f;
#pragma unroll
    for (int j = 0; j < 8; j++) {
        const int jj = tid + j * 256;
        const float zi = zsh[jj];
        const float zf = zsh[HDIM + jj];
        const float zo = zsh[2 * HDIM + jj];
        const float zu = zsh[3 * HDIM + jj];
        const float ig = 1.0f / (1.0f + expf(-zi));
        const float fg = 1.0f / (1.0f + expf(-zf));
        const float og = 1.0f / (1.0f + expf(-zo));
        const float ug = tanhf(zu);
        const float cold = c_st[bb * HDIM + jj] * keep;
        const float c = fg * cold + ig * ug;
        cv[j] = c; ov[j] = og; s2 += c;
    }

    // LN over c row (width H)
    const float mean2 = block_reduce_sum(s2, sbuf) * (1.0f / HDIM);
    float sq2 = 0.0f;
#pragma unroll
    for (int j = 0; j < 8; j++) { float d = cv[j] - mean2; sq2 += d * d; }
    const float var2 = block_reduce_sum(sq2, sbuf) * (1.0f / HDIM);
    const float rstd2 = rsqrtf(var2 + LN_EPS);

#pragma unroll
    for (int j = 0; j < 8; j++) {
        const int jj = tid + j * 256;
        const float h = ov[j] * tanhf((cv[j] - mean2) * rstd2 * gc[jj] + bc[jj]);
        c_st[bb * HDIM + jj] = cv[j];
        h_st[bb * HDIM + jj] = h;
        hs_out[(size_t)bb * HDIM + jj] = h;
    }
}

// ---------------------------------------------------------------------------
// State init + final state pack
// ---------------------------------------------------------------------------
__global__ void init_state_kernel(const float* __restrict__ init,
                                  float* __restrict__ c_st, float* __restrict__ h_st)
{
    const int idx = blockIdx.x * blockDim.x + threadIdx.x;
    if (idx >= BATCH * HDIM) return;
    const int b = idx / HDIM, j = idx % HDIM;
    const size_t base = (size_t)b * T_STEPS * 2 * HDIM;  // row b*T of (B*T, 2H)
    c_st[idx] = init[base + j];
    h_st[idx] = init[base + HDIM + j];
}

__global__ void write_s_kernel(const float* __restrict__ c_st,
                               const float* __restrict__ h_st,
                               float* __restrict__ s_out)
{
    const int idx = blockIdx.x * blockDim.x + threadIdx.x;
    if (idx >= BATCH * 2 * HDIM) return;
    const int b = idx / (2 * HDIM), j = idx % (2 * HDIM);
    s_out[idx] = (j < HDIM) ? c_st[b * HDIM + j] : h_st[b * HDIM + (j - HDIM)];
}

// ---------------------------------------------------------------------------
// Launch
// ---------------------------------------------------------------------------
extern "C" void kernel_launch(void* const* d_in, const int* in_sizes, int n_in,
                              void* d_out, int out_size)
{
    const float* x    = (const float*)d_in[0];   // (T,B,NIN)
    const float* mask = (const float*)d_in[1];   // (T,B,1)
    const float* init = (const float*)d_in[2];   // (B*T, 2H)
    const float* wx   = (const float*)d_in[3];   // (NIN, 4H)
    const float* wh   = (const float*)d_in[4];   // (H, 4H)
    const float* bias = (const float*)d_in[5];   // (4H,)
    const float* gx   = (const float*)d_in[6];
    const float* bx   = (const float*)d_in[7];
    const float* gh   = (const float*)d_in[8];
    const float* bh   = (const float*)d_in[9];
    const float* gc   = (const float*)d_in[10];
    const float* bc   = (const float*)d_in[11];

    float* out   = (float*)d_out;
    float* hs    = out;                                    // (T,B,H)
    float* s_out = out + (size_t)T_STEPS * BATCH * HDIM;   // (B,2H)

    float *zx, *gw, *c_st, *h_st;
    cudaGetSymbolAddress((void**)&zx, g_zx);
    cudaGetSymbolAddress((void**)&gw, g_gw);
    cudaGetSymbolAddress((void**)&c_st, g_c);
    cudaGetSymbolAddress((void**)&h_st, g_h);

    // Phase 1: zx_raw = X @ wx   (16384 x 8192, K=1024)
    sgemm_kernel<<<dim3(G4 / 128, (T_STEPS * BATCH) / 128), 256>>>(
        x, wx, zx, T_STEPS * BATCH, G4, NINF, nullptr);

    // Phase 2: in-place LN of every zx row
    ln_rows_kernel<<<T_STEPS * BATCH, 256>>>(zx, gx, bx);

    // State init
    init_state_kernel<<<(BATCH * HDIM + 255) / 256, 256>>>(init, c_st, h_st);

    // Sequential scan
    for (int t = 0; t < T_STEPS; t++) {
        // gw = (h * (1-m_t)) @ wh   (256 x 8192, K=2048)
        sgemm_kernel<<<dim3(G4 / 128, BATCH / 128), 256>>>(
            h_st, wh, gw, BATCH, G4, HDIM, mask + (size_t)t * BATCH);

        lstm_step_kernel<<<BATCH, 256>>>(
            gw, zx + (size_t)t * BATCH * G4, mask + (size_t)t * BATCH,
            bias, gh, bh, gc, bc, c_st, h_st,
            hs + (size_t)t * BATCH * HDIM);
    }

    // Final state pack
    write_s_kernel<<<(BATCH * 2 * HDIM + 255) / 256, 256>>>(c_st, h_st, s_out);
}

// round 6
// speedup vs baseline: 2.7886x; 2.7886x over previous
#include <cuda_runtime.h>
#include <cuda_bf16.h>
#include <cstdint>
#include <cstddef>

// Problem constants
#define T_STEPS 64
#define BATCH   256
#define NINF    1024
#define HDIM    2048
#define G4      8192          // 4*H
#define KPH     (3*HDIM)      // 6144  split-K' for recurrent
#define KPX     (3*NINF)      // 3072  split-K' for input proj
#define LN_EPS  1e-5f

// ---------------------------------------------------------------------------
// Device global scratch (allocation-free rule)
// ---------------------------------------------------------------------------
__device__ float g_zx[(size_t)T_STEPS * BATCH * G4];   // LN(x@wx) fp32 (512 MB)
__device__ float g_gw[(size_t)BATCH * G4];             // h@wh current step
__device__ float g_c[BATCH * HDIM];
__device__ float g_h[BATCH * HDIM];
__device__ __nv_bfloat16 g_ah[(size_t)BATCH * KPH];            // split h (per step)
__device__ __nv_bfloat16 g_ax[(size_t)T_STEPS * BATCH * KPX];  // split x (100 MB)
__device__ __nv_bfloat16 g_bwh[(size_t)G4 * KPH];              // split wh^T (100 MB)
__device__ __nv_bfloat16 g_bwx[(size_t)G4 * KPX];              // split wx^T (50 MB)

// ---------------------------------------------------------------------------
// Arch-neutral PTX helpers (sm_80-era: mma.sync / ldmatrix / cp.async)
// ---------------------------------------------------------------------------
__device__ __forceinline__ uint32_t smem_u32(const void* p) {
    uint32_t a;
    asm("{ .reg .u64 t; cvta.to.shared.u64 t, %1; cvt.u32.u64 %0, t; }"
        : "=r"(a) : "l"(p));
    return a;
}
__device__ __forceinline__ void ldsm4(uint32_t& r0, uint32_t& r1,
                                      uint32_t& r2, uint32_t& r3, uint32_t addr) {
    asm volatile("ldmatrix.sync.aligned.m8n8.x4.shared.b16 {%0,%1,%2,%3}, [%4];"
                 : "=r"(r0), "=r"(r1), "=r"(r2), "=r"(r3) : "r"(addr));
}
__device__ __forceinline__ void mma16816(float* c, const uint32_t* a,
                                         uint32_t b0, uint32_t b1) {
    asm volatile("mma.sync.aligned.m16n8k16.row.col.f32.bf16.bf16.f32 "
                 "{%0,%1,%2,%3}, {%4,%5,%6,%7}, {%8,%9}, {%0,%1,%2,%3};"
                 : "+f"(c[0]), "+f"(c[1]), "+f"(c[2]), "+f"(c[3])
                 : "r"(a[0]), "r"(a[1]), "r"(a[2]), "r"(a[3]), "r"(b0), "r"(b1));
}
__device__ __forceinline__ void cp16(uint32_t s, const void* g) {
    asm volatile("cp.async.cg.shared.global [%0], [%1], 16;" :: "r"(s), "l"(g));
}
#define CP_COMMIT() asm volatile("cp.async.commit_group;" ::: "memory")
#define CP_WAIT0()  asm volatile("cp.async.wait_group 0;" ::: "memory")

// ---------------------------------------------------------------------------
// mma.sync bf16 GEMM:  C[M,N] = A[M,Kp] @ B[N,Kp]^T, fp32 accum/out.
// CTA tile 128x128, 8 warps (64x32 warp tiles), K chunk 64, cp.async 2-stage.
// Smem rows padded to 72 bf16 (144 B): conflict-free ldmatrix (16B*i mod 128
// distinct over 8 rows). grid = (N/128, M/128), block = 256.
// ---------------------------------------------------------------------------
#define RSTRIDE 144          // bytes per smem row (64 bf16 data + 8 pad)
#define STAGE_B (128 * RSTRIDE)   // 18432 bytes per tile

__global__ __launch_bounds__(256) void mma_gemm_kernel(
    const __nv_bfloat16* __restrict__ A, const __nv_bfloat16* __restrict__ B,
    float* __restrict__ C, int N, int Kp)
{
    extern __shared__ char smem[];
    const int tid = threadIdx.x, lane = tid & 31, wid = tid >> 5;
    const int warp_m = wid & 1, warp_n = wid >> 1;  // 2 x 4 warp grid
    const int bn = blockIdx.x, bm = blockIdx.y;
    const uint32_t sb = smem_u32(smem);
    // layout: A0 | B0 | A1 | B1
    const uint32_t aoff[2] = { 0u, 2u * STAGE_B };
    const uint32_t boff[2] = { 1u * STAGE_B, 3u * STAGE_B };

    // cp.async load slots: 256 threads x 4 iters cover 128 rows x 4 chunks(16B)
    const int lrow = tid >> 3;          // 0..31
    const int lchunk = tid & 7;         // 0..7  (x16B = 64 bf16)
    const __nv_bfloat16* agp = A + (size_t)(bm * 128 + lrow) * Kp + lchunk * 8;
    const __nv_bfloat16* bgp = B + (size_t)(bn * 128 + lrow) * Kp + lchunk * 8;
    const uint32_t ls_off = (uint32_t)lrow * RSTRIDE + lchunk * 16;

    float acc[4][4][4] = {};

    // preload chunk 0 -> stage 0
#pragma unroll
    for (int i = 0; i < 4; i++) {
        cp16(sb + aoff[0] + ls_off + i * 32 * RSTRIDE, agp + (size_t)i * 32 * Kp);
        cp16(sb + boff[0] + ls_off + i * 32 * RSTRIDE, bgp + (size_t)i * 32 * Kp);
    }
    CP_COMMIT();

    const int NC = Kp >> 6;
    for (int kc = 0; kc < NC; kc++) {
        const int st = kc & 1;
        CP_WAIT0();
        __syncthreads();
        if (kc + 1 < NC) {
            const int k0 = (kc + 1) << 6;
            const int ns = st ^ 1;
#pragma unroll
            for (int i = 0; i < 4; i++) {
                cp16(sb + aoff[ns] + ls_off + i * 32 * RSTRIDE,
                     agp + (size_t)i * 32 * Kp + k0);
                cp16(sb + boff[ns] + ls_off + i * 32 * RSTRIDE,
                     bgp + (size_t)i * 32 * Kp + k0);
            }
            CP_COMMIT();
        }

        const uint32_t ab = sb + aoff[st];
        const uint32_t bb = sb + boff[st];
#pragma unroll
        for (int kk = 0; kk < 4; kk++) {
            const int kb = kk * 16;
            uint32_t af[4][4], bf[2][4];
#pragma unroll
            for (int mt = 0; mt < 4; mt++) {
                const int row = warp_m * 64 + mt * 16 + (lane & 7) + ((lane >> 3) & 1) * 8;
                const int col = kb + (lane >> 4) * 8;
                ldsm4(af[mt][0], af[mt][1], af[mt][2], af[mt][3],
                      ab + row * RSTRIDE + col * 2);
            }
#pragma unroll
            for (int bt = 0; bt < 2; bt++) {
                const int row = warp_n * 32 + bt * 16 + (lane & 7) + (lane >> 4) * 8;
                const int col = kb + ((lane >> 3) & 1) * 8;
                ldsm4(bf[bt][0], bf[bt][1], bf[bt][2], bf[bt][3],
                      bb + row * RSTRIDE + col * 2);
            }
#pragma unroll
            for (int mt = 0; mt < 4; mt++)
#pragma unroll
                for (int nt = 0; nt < 4; nt++)
                    mma16816(acc[mt][nt], af[mt],
                             bf[nt >> 1][(nt & 1) * 2], bf[nt >> 1][(nt & 1) * 2 + 1]);
        }
        // no trailing sync needed: next iteration's leading __syncthreads()
        // (after its wait) precedes any overwrite of this stage.
    }

    // Epilogue: canonical m16n8 C fragment scatter
    float* Cw = C + (size_t)(bm * 128 + warp_m * 64) * N + bn * 128 + warp_n * 32;
    const int tr = lane >> 2, tc = (lane & 3) * 2;
#pragma unroll
    for (int mt = 0; mt < 4; mt++)
#pragma unroll
        for (int nt = 0; nt < 4; nt++) {
            float* p = Cw + (size_t)(mt * 16 + tr) * N + nt * 8 + tc;
            *(float2*)p = make_float2(acc[mt][nt][0], acc[mt][nt][1]);
            *(float2*)(p + (size_t)8 * N) = make_float2(acc[mt][nt][2], acc[mt][nt][3]);
        }
}
#define GEMM_SMEM (4 * STAGE_B)   // 73728 bytes

// ---------------------------------------------------------------------------
// Operand prep: split fp32 into bf16 hi/lo, stacked along K.
// A layout: [hi | lo | hi], B layout: [hi ; hi ; lo]  (A'B' = AhBh+AlBh+AhBl)
// ---------------------------------------------------------------------------
__global__ void transpose_split_kernel(const float* __restrict__ W,
                                       __nv_bfloat16* __restrict__ Bp,
                                       int K, int N)
{
    __shared__ float tile[32][33];
    const int k0 = blockIdx.y * 32, n0 = blockIdx.x * 32;
    const int tx = threadIdx.x, ty = threadIdx.y;   // (32, 8)
#pragma unroll
    for (int i = 0; i < 32; i += 8)
        tile[ty + i][tx] = W[(size_t)(k0 + ty + i) * N + (n0 + tx)];
    __syncthreads();
    const size_t K3 = 3 * (size_t)K;
#pragma unroll
    for (int i = 0; i < 32; i += 8) {
        const int n = n0 + ty + i, k = k0 + tx;
        const float v = tile[tx][ty + i];
        const __nv_bfloat16 hi = __float2bfloat16(v);
        const float lo = v - __bfloat162float(hi);
        __nv_bfloat16* row = Bp + (size_t)n * K3;
        row[k] = hi; row[K + k] = hi; row[2 * K + k] = __float2bfloat16(lo);
    }
}

__global__ void split_a_kernel(const float* __restrict__ X,
                               __nv_bfloat16* __restrict__ Ap,
                               int rows, int K)
{
    const int idx = blockIdx.x * blockDim.x + threadIdx.x;
    if (idx >= rows * K) return;
    const int r = idx / K, k = idx % K;
    const float v = X[idx];
    const __nv_bfloat16 hi = __float2bfloat16(v);
    const float lo = v - __bfloat162float(hi);
    __nv_bfloat16* row = Ap + (size_t)r * (3 * (size_t)K);
    row[k] = hi; row[K + k] = __float2bfloat16(lo); row[2 * K + k] = hi;
}

// ---------------------------------------------------------------------------
// Block reduction (256 threads)
// ---------------------------------------------------------------------------
__device__ __forceinline__ float block_reduce_sum(float v, float* sbuf)
{
#pragma unroll
    for (int o = 16; o > 0; o >>= 1) v += __shfl_down_sync(0xffffffffu, v, o);
    const int lane = threadIdx.x & 31, w = threadIdx.x >> 5;
    if (lane == 0) sbuf[w] = v;
    __syncthreads();
    if (w == 0) {
        v = (lane < 8) ? sbuf[lane] : 0.0f;
#pragma unroll
        for (int o = 16; o > 0; o >>= 1) v += __shfl_down_sync(0xffffffffu, v, o);
        if (lane == 0) sbuf[0] = v;
    }
    __syncthreads();
    v = sbuf[0];
    __syncthreads();
    return v;
}

// ---------------------------------------------------------------------------
// In-place row LayerNorm over width 8192 (LN(x@wx)). 1 CTA / row.
// ---------------------------------------------------------------------------
__global__ __launch_bounds__(256) void ln_rows_kernel(
    float* __restrict__ Z, const float* __restrict__ g, const float* __restrict__ b)
{
    __shared__ float sbuf[32];
    const int tid = threadIdx.x;
    float* row = Z + (size_t)blockIdx.x * G4;

    float v[32];
    float s = 0.0f;
#pragma unroll
    for (int i = 0; i < 32; i++) { v[i] = row[tid + i * 256]; s += v[i]; }
    const float mean = block_reduce_sum(s, sbuf) * (1.0f / G4);
    float sq = 0.0f;
#pragma unroll
    for (int i = 0; i < 32; i++) { float d = v[i] - mean; sq += d * d; }
    const float var = block_reduce_sum(sq, sbuf) * (1.0f / G4);
    const float rstd = rsqrtf(var + LN_EPS);
#pragma unroll
    for (int i = 0; i < 32; i++) {
        const int col = tid + i * 256;
        row[col] = (v[i] - mean) * rstd * g[col] + b[col];
    }
}

// ---------------------------------------------------------------------------
// Per-step fused LSTM pointwise. 1 CTA per batch row.
// Also emits next step's split-A operand (h * keep_{t+1} as bf16 hi/lo/hi).
// ---------------------------------------------------------------------------
__global__ __launch_bounds__(256) void lstm_step_kernel(
    const float* __restrict__ gw, const float* __restrict__ zx_t,
    const float* __restrict__ mask_t, const float* __restrict__ bias,
    const float* __restrict__ gh, const float* __restrict__ bh,
    const float* __restrict__ gc, const float* __restrict__ bc,
    float* __restrict__ c_st, float* __restrict__ h_st,
    float* __restrict__ hs_out,
    __nv_bfloat16* __restrict__ a_next, const float* __restrict__ mask_next)
{
    __shared__ float zsh[G4];
    __shared__ float sbuf[32];

    const int bb = blockIdx.x, tid = threadIdx.x;
    const float* grow = gw + (size_t)bb * G4;
    const float* zrow = zx_t + (size_t)bb * G4;

    float v[32];
    float s = 0.0f;
#pragma unroll
    for (int i = 0; i < 32; i++) { v[i] = grow[tid + i * 256]; s += v[i]; }
    const float mean = block_reduce_sum(s, sbuf) * (1.0f / G4);
    float sq = 0.0f;
#pragma unroll
    for (int i = 0; i < 32; i++) { float d = v[i] - mean; sq += d * d; }
    const float var = block_reduce_sum(sq, sbuf) * (1.0f / G4);
    const float rstd = rsqrtf(var + LN_EPS);

#pragma unroll
    for (int i = 0; i < 32; i++) {
        const int col = tid + i * 256;
        zsh[col] = zrow[col] + (v[i] - mean) * rstd * gh[col] + bh[col] + bias[col];
    }
    __syncthreads();

    const float keep = 1.0f - mask_t[bb];
    float cv[8], ov[8];
    float s2 = 0.0f;
#pragma unroll
    for (int j = 0; j < 8; j++) {
        const int jj = tid + j * 256;
        const float zi = zsh[jj];
        const float zf = zsh[HDIM + jj];
        const float zo = zsh[2 * HDIM + jj];
        const float zu = zsh[3 * HDIM + jj];
        const float ig = 1.0f / (1.0f + expf(-zi));
        const float fg = 1.0f / (1.0f + expf(-zf));
        const float og = 1.0f / (1.0f + expf(-zo));
        const float ug = tanhf(zu);
        const float cold = c_st[bb * HDIM + jj] * keep;
        const float c = fg * cold + ig * ug;
        cv[j] = c; ov[j] = og; s2 += c;
    }

    const float mean2 = block_reduce_sum(s2, sbuf) * (1.0f / HDIM);
    float sq2 = 0.0f;
#pragma unroll
    for (int j = 0; j < 8; j++) { float d = cv[j] - mean2; sq2 += d * d; }
    const float var2 = block_reduce_sum(sq2, sbuf) * (1.0f / HDIM);
    const float rstd2 = rsqrtf(var2 + LN_EPS);

    const float keep_n = a_next ? (1.0f - mask_next[bb]) : 0.0f;
#pragma unroll
    for (int j = 0; j < 8; j++) {
        const int jj = tid + j * 256;
        const float h = ov[j] * tanhf((cv[j] - mean2) * rstd2 * gc[jj] + bc[jj]);
        c_st[bb * HDIM + jj] = cv[j];
        h_st[bb * HDIM + jj] = h;
        hs_out[(size_t)bb * HDIM + jj] = h;
        if (a_next) {
            const float hk = h * keep_n;
            const __nv_bfloat16 hi = __float2bfloat16(hk);
            const float lo = hk - __bfloat162float(hi);
            __nv_bfloat16* row = a_next + (size_t)bb * KPH;
            row[jj] = hi;
            row[HDIM + jj] = __float2bfloat16(lo);
            row[2 * HDIM + jj] = hi;
        }
    }
}

// ---------------------------------------------------------------------------
// State init (also builds step-0 split-A operand) + final state pack
// ---------------------------------------------------------------------------
__global__ void init_state_kernel(const float* __restrict__ init,
                                  const float* __restrict__ mask0,
                                  float* __restrict__ c_st, float* __restrict__ h_st,
                                  __nv_bfloat16* __restrict__ a0)
{
    const int idx = blockIdx.x * blockDim.x + threadIdx.x;
    if (idx >= BATCH * HDIM) return;
    const int b = idx / HDIM, j = idx % HDIM;
    const size_t base = (size_t)b * T_STEPS * 2 * HDIM;
    const float c0 = init[base + j];
    const float h0 = init[base + HDIM + j];
    c_st[idx] = c0;
    h_st[idx] = h0;
    const float hk = h0 * (1.0f - mask0[b]);
    const __nv_bfloat16 hi = __float2bfloat16(hk);
    const float lo = hk - __bfloat162float(hi);
    __nv_bfloat16* row = a0 + (size_t)b * KPH;
    row[j] = hi;
    row[HDIM + j] = __float2bfloat16(lo);
    row[2 * HDIM + j] = hi;
}

__global__ void write_s_kernel(const float* __restrict__ c_st,
                               const float* __restrict__ h_st,
                               float* __restrict__ s_out)
{
    const int idx = blockIdx.x * blockDim.x + threadIdx.x;
    if (idx >= BATCH * 2 * HDIM) return;
    const int b = idx / (2 * HDIM), j = idx % (2 * HDIM);
    s_out[idx] = (j < HDIM) ? c_st[b * HDIM + j] : h_st[b * HDIM + (j - HDIM)];
}

// ---------------------------------------------------------------------------
// Launch
// ---------------------------------------------------------------------------
extern "C" void kernel_launch(void* const* d_in, const int* in_sizes, int n_in,
                              void* d_out, int out_size)
{
    const float* x    = (const float*)d_in[0];   // (T,B,NIN)
    const float* mask = (const float*)d_in[1];   // (T,B,1)
    const float* init = (const float*)d_in[2];   // (B*T, 2H)
    const float* wx   = (const float*)d_in[3];   // (NIN, 4H)
    const float* wh   = (const float*)d_in[4];   // (H, 4H)
    const float* bias = (const float*)d_in[5];
    const float* gx   = (const float*)d_in[6];
    const float* bxv  = (const float*)d_in[7];
    const float* gh   = (const float*)d_in[8];
    const float* bhv  = (const float*)d_in[9];
    const float* gc   = (const float*)d_in[10];
    const float* bc   = (const float*)d_in[11];

    float* out   = (float*)d_out;
    float* hs    = out;
    float* s_out = out + (size_t)T_STEPS * BATCH * HDIM;

    float *zx, *gw, *c_st, *h_st;
    __nv_bfloat16 *ah, *ax, *bwh, *bwx;
    cudaGetSymbolAddress((void**)&zx,  g_zx);
    cudaGetSymbolAddress((void**)&gw,  g_gw);
    cudaGetSymbolAddress((void**)&c_st, g_c);
    cudaGetSymbolAddress((void**)&h_st, g_h);
    cudaGetSymbolAddress((void**)&ah,  g_ah);
    cudaGetSymbolAddress((void**)&ax,  g_ax);
    cudaGetSymbolAddress((void**)&bwh, g_bwh);
    cudaGetSymbolAddress((void**)&bwx, g_bwx);

    cudaFuncSetAttribute(mma_gemm_kernel,
                         cudaFuncAttributeMaxDynamicSharedMemorySize, GEMM_SMEM);

    // Phase 0: operand prep (split fp32 -> stacked bf16)
    transpose_split_kernel<<<dim3(G4 / 32, HDIM / 32), dim3(32, 8)>>>(wh, bwh, HDIM, G4);
    transpose_split_kernel<<<dim3(G4 / 32, NINF / 32), dim3(32, 8)>>>(wx, bwx, NINF, G4);
    split_a_kernel<<<(T_STEPS * BATCH * NINF + 255) / 256, 256>>>(
        x, ax, T_STEPS * BATCH, NINF);

    // Phase 1: zx = X' @ wx'  (16384 x 8192, K'=3072), then in-place LN
    mma_gemm_kernel<<<dim3(G4 / 128, (T_STEPS * BATCH) / 128), 256, GEMM_SMEM>>>(
        ax, bwx, zx, G4, KPX);
    ln_rows_kernel<<<T_STEPS * BATCH, 256>>>(zx, gx, bxv);

    // State init (+ step-0 A operand)
    init_state_kernel<<<(BATCH * HDIM + 255) / 256, 256>>>(init, mask, c_st, h_st, ah);

    // Sequential scan
    for (int t = 0; t < T_STEPS; t++) {
        mma_gemm_kernel<<<dim3(G4 / 128, BATCH / 128), 256, GEMM_SMEM>>>(
            ah, bwh, gw, G4, KPH);

        const bool last = (t == T_STEPS - 1);
        lstm_step_kernel<<<BATCH, 256>>>(
            gw, zx + (size_t)t * BATCH * G4, mask + (size_t)t * BATCH,
            bias, gh, bhv, gc, bc, c_st, h_st,
            hs + (size_t)t * BATCH * HDIM,
            last ? nullptr : ah,
            last ? nullptr : (mask + (size_t)(t + 1) * BATCH));
    }

    write_s_kernel<<<(BATCH * 2 * HDIM + 255) / 256, 256>>>(c_st, h_st, s_out);
}

// round 11
// speedup vs baseline: 3.0262x; 1.0852x over previous
#include <cuda_runtime.h>
#include <cuda_bf16.h>
#include <cstdint>
#include <cstddef>

// Problem constants
#define T_STEPS 64
#define BATCH   256
#define NINF    1024
#define HDIM    2048
#define G4      8192          // 4*H
#define KPH     (3*HDIM)      // 6144  split-K' for recurrent
#define KPX     (3*NINF)      // 3072  split-K' for input proj
#define LN_EPS  1e-5f

// ---------------------------------------------------------------------------
// Device global scratch (allocation-free rule)
// ---------------------------------------------------------------------------
__device__ float g_zx[(size_t)T_STEPS * BATCH * G4];   // LN(x@wx) fp32 (512 MB)
__device__ float g_gw[2 * (size_t)BATCH * G4];         // h@wh partials (16 MB)
__device__ float g_c[BATCH * HDIM];
__device__ float g_h[BATCH * HDIM];
__device__ __nv_bfloat16 g_ah[(size_t)BATCH * KPH];            // split h (per step)
__device__ __nv_bfloat16 g_ax[(size_t)T_STEPS * BATCH * KPX];  // split x (100 MB)
__device__ __nv_bfloat16 g_bwh[(size_t)G4 * KPH];              // split wh^T (100 MB)
__device__ __nv_bfloat16 g_bwx[(size_t)G4 * KPX];              // split wx^T (50 MB)

// ---------------------------------------------------------------------------
// Arch-neutral PTX helpers (sm_80-era: mma.sync / ldmatrix / cp.async)
// ---------------------------------------------------------------------------
__device__ __forceinline__ uint32_t smem_u32(const void* p) {
    uint32_t a;
    asm("{ .reg .u64 t; cvta.to.shared.u64 t, %1; cvt.u32.u64 %0, t; }"
        : "=r"(a) : "l"(p));
    return a;
}
__device__ __forceinline__ void ldsm4(uint32_t& r0, uint32_t& r1,
                                      uint32_t& r2, uint32_t& r3, uint32_t addr) {
    asm volatile("ldmatrix.sync.aligned.m8n8.x4.shared.b16 {%0,%1,%2,%3}, [%4];"
                 : "=r"(r0), "=r"(r1), "=r"(r2), "=r"(r3) : "r"(addr));
}
__device__ __forceinline__ void mma16816(float* c, const uint32_t* a,
                                         uint32_t b0, uint32_t b1) {
    asm volatile("mma.sync.aligned.m16n8k16.row.col.f32.bf16.bf16.f32 "
                 "{%0,%1,%2,%3}, {%4,%5,%6,%7}, {%8,%9}, {%0,%1,%2,%3};"
                 : "+f"(c[0]), "+f"(c[1]), "+f"(c[2]), "+f"(c[3])
                 : "r"(a[0]), "r"(a[1]), "r"(a[2]), "r"(a[3]), "r"(b0), "r"(b1));
}
__device__ __forceinline__ void cp16(uint32_t s, const void* g) {
    asm volatile("cp.async.cg.shared.global [%0], [%1], 16;" :: "r"(s), "l"(g));
}
#define CP_COMMIT() asm volatile("cp.async.commit_group;" ::: "memory")
#define CP_WAIT0()  asm volatile("cp.async.wait_group 0;" ::: "memory")

// ---------------------------------------------------------------------------
// mma.sync bf16 GEMM with optional split-K:
//   C_z[M,N] = A[:, z*Kp:(z+1)*Kp] @ B[:, z*Kp:(z+1)*Kp]^T   (z = blockIdx.z)
// A rows length Krow; per-slice K = Kp. C_z = C + z*cstride.
// CTA tile 128x128, 8 warps (64x32 warp tiles), K chunk 64, cp.async 2-stage.
// Smem rows padded to 144 B: conflict-free ldmatrix.
// grid = (N/128, M/128, slices), block = 256.
// ---------------------------------------------------------------------------
#define RSTRIDE 144               // bytes per smem row (64 bf16 data + 8 pad)
#define STAGE_B (128 * RSTRIDE)   // 18432 bytes per tile

__global__ __launch_bounds__(256) void mma_gemm_kernel(
    const __nv_bfloat16* __restrict__ A, const __nv_bfloat16* __restrict__ B,
    float* __restrict__ C, int N, int Krow, int Kp, size_t cstride)
{
    extern __shared__ char smem[];
    const int tid = threadIdx.x, lane = tid & 31, wid = tid >> 5;
    const int warp_m = wid & 1, warp_n = wid >> 1;  // 2 x 4 warp grid
    const int bn = blockIdx.x, bm = blockIdx.y, kz = blockIdx.z;
    const uint32_t sb = smem_u32(smem);
    // layout: A0 | B0 | A1 | B1
    const uint32_t aoff[2] = { 0u, 2u * STAGE_B };
    const uint32_t boff[2] = { 1u * STAGE_B, 3u * STAGE_B };

    C += (size_t)kz * cstride;

    // cp.async load slots: 256 threads x 4 iters cover 128 rows x 8 chunks(16B)
    const int lrow = tid >> 3;          // 0..31
    const int lchunk = tid & 7;         // 0..7  (x16B = 64 bf16)
    const __nv_bfloat16* agp =
        A + (size_t)(bm * 128 + lrow) * Krow + (size_t)kz * Kp + lchunk * 8;
    const __nv_bfloat16* bgp =
        B + (size_t)(bn * 128 + lrow) * Krow + (size_t)kz * Kp + lchunk * 8;
    const uint32_t ls_off = (uint32_t)lrow * RSTRIDE + lchunk * 16;

    float acc[4][4][4] = {};

    // preload chunk 0 -> stage 0
#pragma unroll
    for (int i = 0; i < 4; i++) {
        cp16(sb + aoff[0] + ls_off + i * 32 * RSTRIDE, agp + (size_t)i * 32 * Krow);
        cp16(sb + boff[0] + ls_off + i * 32 * RSTRIDE, bgp + (size_t)i * 32 * Krow);
    }
    CP_COMMIT();

    const int NC = Kp >> 6;
    for (int kc = 0; kc < NC; kc++) {
        const int st = kc & 1;
        CP_WAIT0();
        __syncthreads();
        if (kc + 1 < NC) {
            const int k0 = (kc + 1) << 6;
            const int ns = st ^ 1;
#pragma unroll
            for (int i = 0; i < 4; i++) {
                cp16(sb + aoff[ns] + ls_off + i * 32 * RSTRIDE,
                     agp + (size_t)i * 32 * Krow + k0);
                cp16(sb + boff[ns] + ls_off + i * 32 * RSTRIDE,
                     bgp + (size_t)i * 32 * Krow + k0);
            }
            CP_COMMIT();
        }

        const uint32_t ab = sb + aoff[st];
        const uint32_t bb = sb + boff[st];
#pragma unroll
        for (int kk = 0; kk < 4; kk++) {
            const int kb = kk * 16;
            uint32_t af[4][4], bf[2][4];
#pragma unroll
            for (int mt = 0; mt < 4; mt++) {
                const int row = warp_m * 64 + mt * 16 + (lane & 7) + ((lane >> 3) & 1) * 8;
                const int col = kb + (lane >> 4) * 8;
                ldsm4(af[mt][0], af[mt][1], af[mt][2], af[mt][3],
                      ab + row * RSTRIDE + col * 2);
            }
#pragma unroll
            for (int bt = 0; bt < 2; bt++) {
                const int row = warp_n * 32 + bt * 16 + (lane & 7) + (lane >> 4) * 8;
                const int col = kb + ((lane >> 3) & 1) * 8;
                ldsm4(bf[bt][0], bf[bt][1], bf[bt][2], bf[bt][3],
                      bb + row * RSTRIDE + col * 2);
            }
#pragma unroll
            for (int mt = 0; mt < 4; mt++)
#pragma unroll
                for (int nt = 0; nt < 4; nt++)
                    mma16816(acc[mt][nt], af[mt],
                             bf[nt >> 1][(nt & 1) * 2], bf[nt >> 1][(nt & 1) * 2 + 1]);
        }
        // next iteration's leading wait+sync protects this stage before reuse
    }

    // Epilogue: canonical m16n8 C fragment scatter
    float* Cw = C + (size_t)(bm * 128 + warp_m * 64) * N + bn * 128 + warp_n * 32;
    const int tr = lane >> 2, tc = (lane & 3) * 2;
#pragma unroll
    for (int mt = 0; mt < 4; mt++)
#pragma unroll
        for (int nt = 0; nt < 4; nt++) {
            float* p = Cw + (size_t)(mt * 16 + tr) * N + nt * 8 + tc;
            *(float2*)p = make_float2(acc[mt][nt][0], acc[mt][nt][1]);
            *(float2*)(p + (size_t)8 * N) = make_float2(acc[mt][nt][2], acc[mt][nt][3]);
        }
}
#define GEMM_SMEM (4 * STAGE_B)   // 73728 bytes

// ---------------------------------------------------------------------------
// Operand prep: split fp32 into bf16 hi/lo, stacked along K.
// A layout: [hi | lo | hi], B layout: [hi ; hi ; lo]  (A'B' = AhBh+AlBh+AhBl)
// ---------------------------------------------------------------------------
__global__ void transpose_split_kernel(const float* __restrict__ W,
                                       __nv_bfloat16* __restrict__ Bp,
                                       int K, int N)
{
    __shared__ float tile[32][33];
    const int k0 = blockIdx.y * 32, n0 = blockIdx.x * 32;
    const int tx = threadIdx.x, ty = threadIdx.y;   // (32, 8)
#pragma unroll
    for (int i = 0; i < 32; i += 8)
        tile[ty + i][tx] = W[(size_t)(k0 + ty + i) * N + (n0 + tx)];
    __syncthreads();
    const size_t K3 = 3 * (size_t)K;
#pragma unroll
    for (int i = 0; i < 32; i += 8) {
        const int n = n0 + ty + i, k = k0 + tx;
        const float v = tile[tx][ty + i];
        const __nv_bfloat16 hi = __float2bfloat16(v);
        const float lo = v - __bfloat162float(hi);
        __nv_bfloat16* row = Bp + (size_t)n * K3;
        row[k] = hi; row[K + k] = hi; row[2 * K + k] = __float2bfloat16(lo);
    }
}

__global__ void split_a_kernel(const float* __restrict__ X,
                               __nv_bfloat16* __restrict__ Ap,
                               int rows, int K)
{
    const int idx = blockIdx.x * blockDim.x + threadIdx.x;
    if (idx >= rows * K) return;
    const int r = idx / K, k = idx % K;
    const float v = X[idx];
    const __nv_bfloat16 hi = __float2bfloat16(v);
    const float lo = v - __bfloat162float(hi);
    __nv_bfloat16* row = Ap + (size_t)r * (3 * (size_t)K);
    row[k] = hi; row[K + k] = __float2bfloat16(lo); row[2 * K + k] = hi;
}

// ---------------------------------------------------------------------------
// Block reduction (256 threads)
// ---------------------------------------------------------------------------
__device__ __forceinline__ float block_reduce_sum(float v, float* sbuf)
{
#pragma unroll
    for (int o = 16; o > 0; o >>= 1) v += __shfl_down_sync(0xffffffffu, v, o);
    const int lane = threadIdx.x & 31, w = threadIdx.x >> 5;
    if (lane == 0) sbuf[w] = v;
    __syncthreads();
    if (w == 0) {
        v = (lane < 8) ? sbuf[lane] : 0.0f;
#pragma unroll
        for (int o = 16; o > 0; o >>= 1) v += __shfl_down_sync(0xffffffffu, v, o);
        if (lane == 0) sbuf[0] = v;
    }
    __syncthreads();
    v = sbuf[0];
    __syncthreads();
    return v;
}

// ---------------------------------------------------------------------------
// In-place row LayerNorm over width 8192 (LN(x@wx)). 1 CTA / row.
// ---------------------------------------------------------------------------
__global__ __launch_bounds__(256) void ln_rows_kernel(
    float* __restrict__ Z, const float* __restrict__ g, const float* __restrict__ b)
{
    __shared__ float sbuf[32];
    const int tid = threadIdx.x;
    float* row = Z + (size_t)blockIdx.x * G4;

    float v[32];
    float s = 0.0f;
#pragma unroll
    for (int i = 0; i < 32; i++) { v[i] = row[tid + i * 256]; s += v[i]; }
    const float mean = block_reduce_sum(s, sbuf) * (1.0f / G4);
    float sq = 0.0f;
#pragma unroll
    for (int i = 0; i < 32; i++) { float d = v[i] - mean; sq += d * d; }
    const float var = block_reduce_sum(sq, sbuf) * (1.0f / G4);
    const float rstd = rsqrtf(var + LN_EPS);
#pragma unroll
    for (int i = 0; i < 32; i++) {
        const int col = tid + i * 256;
        row[col] = (v[i] - mean) * rstd * g[col] + b[col];
    }
}

// ---------------------------------------------------------------------------
// Per-step fused LSTM pointwise. 1 CTA per batch row.
// Sums the two split-K GEMM partials, then LN/gates/state update.
// Also emits next step's split-A operand (h * keep_{t+1} as bf16 hi/lo/hi).
// ---------------------------------------------------------------------------
__global__ __launch_bounds__(256) void lstm_step_kernel(
    const float* __restrict__ gw0, const float* __restrict__ gw1,
    const float* __restrict__ zx_t,
    const float* __restrict__ mask_t, const float* __restrict__ bias,
    const float* __restrict__ gh, const float* __restrict__ bh,
    const float* __restrict__ gc, const float* __restrict__ bc,
    float* __restrict__ c_st, float* __restrict__ h_st,
    float* __restrict__ hs_out,
    __nv_bfloat16* __restrict__ a_next, const float* __restrict__ mask_next)
{
    __shared__ float zsh[G4];
    __shared__ float sbuf[32];

    const int bb = blockIdx.x, tid = threadIdx.x;
    const float* grow0 = gw0 + (size_t)bb * G4;
    const float* grow1 = gw1 + (size_t)bb * G4;
    const float* zrow = zx_t + (size_t)bb * G4;

    float v[32];
    float s = 0.0f;
#pragma unroll
    for (int i = 0; i < 32; i++) {
        v[i] = grow0[tid + i * 256] + grow1[tid + i * 256];
        s += v[i];
    }
    const float mean = block_reduce_sum(s, sbuf) * (1.0f / G4);
    float sq = 0.0f;
#pragma unroll
    for (int i = 0; i < 32; i++) { float d = v[i] - mean; sq += d * d; }
    const float var = block_reduce_sum(sq, sbuf) * (1.0f / G4);
    const float rstd = rsqrtf(var + LN_EPS);

#pragma unroll
    for (int i = 0; i < 32; i++) {
        const int col = tid + i * 256;
        zsh[col] = zrow[col] + (v[i] - mean) * rstd * gh[col] + bh[col] + bias[col];
    }
    __syncthreads();

    const float keep = 1.0f - mask_t[bb];
    float cv[8], ov[8];
    float s2 = 0.0f;
#pragma unroll
    for (int j = 0; j < 8; j++) {
        const int jj = tid + j * 256;
        const float zi = zsh[jj];
        const float zf = zsh[HDIM + jj];
        const float zo = zsh[2 * HDIM + jj];
        const float zu = zsh[3 * HDIM + jj];
        const float ig = 1.0f / (1.0f + expf(-zi));
        const float fg = 1.0f / (1.0f + expf(-zf));
        const float og = 1.0f / (1.0f + expf(-zo));
        const float ug = tanhf(zu);
        const float cold = c_st[bb * HDIM + jj] * keep;
        const float c = fg * cold + ig * ug;
        cv[j] = c; ov[j] = og; s2 += c;
    }

    const float mean2 = block_reduce_sum(s2, sbuf) * (1.0f / HDIM);
    float sq2 = 0.0f;
#pragma unroll
    for (int j = 0; j < 8; j++) { float d = cv[j] - mean2; sq2 += d * d; }
    const float var2 = block_reduce_sum(sq2, sbuf) * (1.0f / HDIM);
    const float rstd2 = rsqrtf(var2 + LN_EPS);

    const float keep_n = a_next ? (1.0f - mask_next[bb]) : 0.0f;
#pragma unroll
    for (int j = 0; j < 8; j++) {
        const int jj = tid + j * 256;
        const float h = ov[j] * tanhf((cv[j] - mean2) * rstd2 * gc[jj] + bc[jj]);
        c_st[bb * HDIM + jj] = cv[j];
        h_st[bb * HDIM + jj] = h;
        hs_out[(size_t)bb * HDIM + jj] = h;
        if (a_next) {
            const float hk = h * keep_n;
            const __nv_bfloat16 hi = __float2bfloat16(hk);
            const float lo = hk - __bfloat162float(hi);
            __nv_bfloat16* row = a_next + (size_t)bb * KPH;
            row[jj] = hi;
            row[HDIM + jj] = __float2bfloat16(lo);
            row[2 * HDIM + jj] = hi;
        }
    }
}

// ---------------------------------------------------------------------------
// State init (also builds step-0 split-A operand) + final state pack
// ---------------------------------------------------------------------------
__global__ void init_state_kernel(const float* __restrict__ init,
                                  const float* __restrict__ mask0,
                                  float* __restrict__ c_st, float* __restrict__ h_st,
                                  __nv_bfloat16* __restrict__ a0)
{
    const int idx = blockIdx.x * blockDim.x + threadIdx.x;
    if (idx >= BATCH * HDIM) return;
    const int b = idx / HDIM, j = idx % HDIM;
    const size_t base = (size_t)b * T_STEPS * 2 * HDIM;
    const float c0 = init[base + j];
    const float h0 = init[base + HDIM + j];
    c_st[idx] = c0;
    h_st[idx] = h0;
    const float hk = h0 * (1.0f - mask0[b]);
    const __nv_bfloat16 hi = __float2bfloat16(hk);
    const float lo = hk - __bfloat162float(hi);
    __nv_bfloat16* row = a0 + (size_t)b * KPH;
    row[j] = hi;
    row[HDIM + j] = __float2bfloat16(lo);
    row[2 * HDIM + j] = hi;
}

__global__ void write_s_kernel(const float* __restrict__ c_st,
                               const float* __restrict__ h_st,
                               float* __restrict__ s_out)
{
    const int idx = blockIdx.x * blockDim.x + threadIdx.x;
    if (idx >= BATCH * 2 * HDIM) return;
    const int b = idx / (2 * HDIM), j = idx % (2 * HDIM);
    s_out[idx] = (j < HDIM) ? c_st[b * HDIM + j] : h_st[b * HDIM + (j - HDIM)];
}

// ---------------------------------------------------------------------------
// Launch
// ---------------------------------------------------------------------------
extern "C" void kernel_launch(void* const* d_in, const int* in_sizes, int n_in,
                              void* d_out, int out_size)
{
    const float* x    = (const float*)d_in[0];   // (T,B,NIN)
    const float* mask = (const float*)d_in[1];   // (T,B,1)
    const float* init = (const float*)d_in[2];   // (B*T, 2H)
    const float* wx   = (const float*)d_in[3];   // (NIN, 4H)
    const float* wh   = (const float*)d_in[4];   // (H, 4H)
    const float* bias = (const float*)d_in[5];
    const float* gx   = (const float*)d_in[6];
    const float* bxv  = (const float*)d_in[7];
    const float* gh   = (const float*)d_in[8];
    const float* bhv  = (const float*)d_in[9];
    const float* gc   = (const float*)d_in[10];
    const float* bc   = (const float*)d_in[11];

    float* out   = (float*)d_out;
    float* hs    = out;
    float* s_out = out + (size_t)T_STEPS * BATCH * HDIM;

    float *zx, *gw, *c_st, *h_st;
    __nv_bfloat16 *ah, *ax, *bwh, *bwx;
    cudaGetSymbolAddress((void**)&zx,  g_zx);
    cudaGetSymbolAddress((void**)&gw,  g_gw);
    cudaGetSymbolAddress((void**)&c_st, g_c);
    cudaGetSymbolAddress((void**)&h_st, g_h);
    cudaGetSymbolAddress((void**)&ah,  g_ah);
    cudaGetSymbolAddress((void**)&ax,  g_ax);
    cudaGetSymbolAddress((void**)&bwh, g_bwh);
    cudaGetSymbolAddress((void**)&bwx, g_bwx);

    const size_t GW_STRIDE = (size_t)BATCH * G4;

    cudaFuncSetAttribute(mma_gemm_kernel,
                         cudaFuncAttributeMaxDynamicSharedMemorySize, GEMM_SMEM);

    // Phase 0: operand prep (split fp32 -> stacked bf16)
    transpose_split_kernel<<<dim3(G4 / 32, HDIM / 32), dim3(32, 8)>>>(wh, bwh, HDIM, G4);
    transpose_split_kernel<<<dim3(G4 / 32, NINF / 32), dim3(32, 8)>>>(wx, bwx, NINF, G4);
    split_a_kernel<<<(T_STEPS * BATCH * NINF + 255) / 256, 256>>>(
        x, ax, T_STEPS * BATCH, NINF);

    // Phase 1: zx = X' @ wx'  (16384 x 8192, K'=3072), then in-place LN
    mma_gemm_kernel<<<dim3(G4 / 128, (T_STEPS * BATCH) / 128, 1), 256, GEMM_SMEM>>>(
        ax, bwx, zx, G4, KPX, KPX, 0);
    ln_rows_kernel<<<T_STEPS * BATCH, 256>>>(zx, gx, bxv);

    // State init (+ step-0 A operand)
    init_state_kernel<<<(BATCH * HDIM + 255) / 256, 256>>>(init, mask, c_st, h_st, ah);

    // Sequential scan: split-K=2 recurrent GEMM (256 CTAs, one wave) + pointwise
    for (int t = 0; t < T_STEPS; t++) {
        mma_gemm_kernel<<<dim3(G4 / 128, BATCH / 128, 2), 256, GEMM_SMEM>>>(
            ah, bwh, gw, G4, KPH, KPH / 2, GW_STRIDE);

        const bool last = (t == T_STEPS - 1);
        lstm_step_kernel<<<BATCH, 256>>>(
            gw, gw + GW_STRIDE,
            zx + (size_t)t * BATCH * G4, mask + (size_t)t * BATCH,
            bias, gh, bhv, gc, bc, c_st, h_st,
            hs + (size_t)t * BATCH * HDIM,
            last ? nullptr : ah,
            last ? nullptr : (mask + (size_t)(t + 1) * BATCH));
    }

    write_s_kernel<<<(BATCH * 2 * HDIM + 255) / 256, 256>>>(c_st, h_st, s_out);
}

// round 13
// speedup vs baseline: 3.2629x; 1.0782x over previous
#include <cuda_runtime.h>
#include <cuda_bf16.h>
#include <cstdint>
#include <cstddef>

// Problem constants
#define T_STEPS 64
#define BATCH   256
#define NINF    1024
#define HDIM    2048
#define G4      8192          // 4*H
#define KPH     (3*HDIM)      // 6144  split-K' for recurrent
#define KPX     (3*NINF)      // 3072  split-K' for input proj
#define LN_EPS  1e-5f

// ---------------------------------------------------------------------------
// Device global scratch (allocation-free rule)
// ---------------------------------------------------------------------------
__device__ float g_zx[(size_t)T_STEPS * BATCH * G4];   // LN(x@wx) fp32 (512 MB)
__device__ float g_gw[2 * (size_t)BATCH * G4];         // h@wh partials (16 MB)
__device__ float g_c[BATCH * HDIM];
__device__ float g_h[BATCH * HDIM];
__device__ __nv_bfloat16 g_ah[(size_t)BATCH * KPH];            // split h (per step)
__device__ __nv_bfloat16 g_ax[(size_t)T_STEPS * BATCH * KPX];  // split x (100 MB)
__device__ __nv_bfloat16 g_bwh[(size_t)G4 * KPH];              // split wh^T (100 MB)
__device__ __nv_bfloat16 g_bwx[(size_t)G4 * KPX];              // split wx^T (50 MB)

// ---------------------------------------------------------------------------
// Arch-neutral PTX helpers (sm_80-era: mma.sync / ldmatrix / cp.async)
// ---------------------------------------------------------------------------
__device__ __forceinline__ uint32_t smem_u32(const void* p) {
    uint32_t a;
    asm("{ .reg .u64 t; cvta.to.shared.u64 t, %1; cvt.u32.u64 %0, t; }"
        : "=r"(a) : "l"(p));
    return a;
}
__device__ __forceinline__ void ldsm4(uint32_t& r0, uint32_t& r1,
                                      uint32_t& r2, uint32_t& r3, uint32_t addr) {
    asm volatile("ldmatrix.sync.aligned.m8n8.x4.shared.b16 {%0,%1,%2,%3}, [%4];"
                 : "=r"(r0), "=r"(r1), "=r"(r2), "=r"(r3) : "r"(addr));
}
__device__ __forceinline__ void mma16816(float* c, const uint32_t* a,
                                         uint32_t b0, uint32_t b1) {
    asm volatile("mma.sync.aligned.m16n8k16.row.col.f32.bf16.bf16.f32 "
                 "{%0,%1,%2,%3}, {%4,%5,%6,%7}, {%8,%9}, {%0,%1,%2,%3};"
                 : "+f"(c[0]), "+f"(c[1]), "+f"(c[2]), "+f"(c[3])
                 : "r"(a[0]), "r"(a[1]), "r"(a[2]), "r"(a[3]), "r"(b0), "r"(b1));
}
__device__ __forceinline__ void cp16(uint32_t s, const void* g) {
    asm volatile("cp.async.cg.shared.global [%0], [%1], 16;" :: "r"(s), "l"(g));
}
#define CP_COMMIT() asm volatile("cp.async.commit_group;" ::: "memory")
#define CP_WAIT0()  asm volatile("cp.async.wait_group 0;" ::: "memory")

// ---------------------------------------------------------------------------
// mma.sync bf16 GEMM with optional split-K:
//   C_z[M,N] = A[:, z*Kp:(z+1)*Kp] @ B[:, z*Kp:(z+1)*Kp]^T   (z = blockIdx.z)
// A rows length Krow; per-slice K = Kp. C_z = C + z*cstride.
// CTA tile 128x128, 8 warps (64x32 warp tiles), K chunk 64, cp.async 2-stage.
// Smem rows padded to 144 B: conflict-free ldmatrix.
// grid = (N/128, M/128, slices), block = 256.  Target 2 CTAs/SM (carveout 100%).
// ---------------------------------------------------------------------------
#define RSTRIDE 144               // bytes per smem row (64 bf16 data + 8 pad)
#define STAGE_B (128 * RSTRIDE)   // 18432 bytes per tile

__global__ __launch_bounds__(256, 2) void mma_gemm_kernel(
    const __nv_bfloat16* __restrict__ A, const __nv_bfloat16* __restrict__ B,
    float* __restrict__ C, int N, int Krow, int Kp, size_t cstride)
{
    extern __shared__ char smem[];
    const int tid = threadIdx.x, lane = tid & 31, wid = tid >> 5;
    const int warp_m = wid & 1, warp_n = wid >> 1;  // 2 x 4 warp grid
    const int bn = blockIdx.x, bm = blockIdx.y, kz = blockIdx.z;
    const uint32_t sb = smem_u32(smem);
    // layout: A0 | B0 | A1 | B1
    const uint32_t aoff[2] = { 0u, 2u * STAGE_B };
    const uint32_t boff[2] = { 1u * STAGE_B, 3u * STAGE_B };

    C += (size_t)kz * cstride;

    // cp.async load slots: 256 threads x 4 iters cover 128 rows x 8 chunks(16B)
    const int lrow = tid >> 3;          // 0..31
    const int lchunk = tid & 7;         // 0..7  (x16B = 64 bf16)
    const __nv_bfloat16* agp =
        A + (size_t)(bm * 128 + lrow) * Krow + (size_t)kz * Kp + lchunk * 8;
    const __nv_bfloat16* bgp =
        B + (size_t)(bn * 128 + lrow) * Krow + (size_t)kz * Kp + lchunk * 8;
    const uint32_t ls_off = (uint32_t)lrow * RSTRIDE + lchunk * 16;

    float acc[4][4][4] = {};

    // preload chunk 0 -> stage 0
#pragma unroll
    for (int i = 0; i < 4; i++) {
        cp16(sb + aoff[0] + ls_off + i * 32 * RSTRIDE, agp + (size_t)i * 32 * Krow);
        cp16(sb + boff[0] + ls_off + i * 32 * RSTRIDE, bgp + (size_t)i * 32 * Krow);
    }
    CP_COMMIT();

    const int NC = Kp >> 6;
    for (int kc = 0; kc < NC; kc++) {
        const int st = kc & 1;
        CP_WAIT0();
        __syncthreads();
        if (kc + 1 < NC) {
            const int k0 = (kc + 1) << 6;
            const int ns = st ^ 1;
#pragma unroll
            for (int i = 0; i < 4; i++) {
                cp16(sb + aoff[ns] + ls_off + i * 32 * RSTRIDE,
                     agp + (size_t)i * 32 * Krow + k0);
                cp16(sb + boff[ns] + ls_off + i * 32 * RSTRIDE,
                     bgp + (size_t)i * 32 * Krow + k0);
            }
            CP_COMMIT();
        }

        const uint32_t ab = sb + aoff[st];
        const uint32_t bb = sb + boff[st];
#pragma unroll
        for (int kk = 0; kk < 4; kk++) {
            const int kb = kk * 16;
            uint32_t af[4][4], bf[2][4];
#pragma unroll
            for (int mt = 0; mt < 4; mt++) {
                const int row = warp_m * 64 + mt * 16 + (lane & 7) + ((lane >> 3) & 1) * 8;
                const int col = kb + (lane >> 4) * 8;
                ldsm4(af[mt][0], af[mt][1], af[mt][2], af[mt][3],
                      ab + row * RSTRIDE + col * 2);
            }
#pragma unroll
            for (int bt = 0; bt < 2; bt++) {
                const int row = warp_n * 32 + bt * 16 + (lane & 7) + (lane >> 4) * 8;
                const int col = kb + ((lane >> 3) & 1) * 8;
                ldsm4(bf[bt][0], bf[bt][1], bf[bt][2], bf[bt][3],
                      bb + row * RSTRIDE + col * 2);
            }
#pragma unroll
            for (int mt = 0; mt < 4; mt++)
#pragma unroll
                for (int nt = 0; nt < 4; nt++)
                    mma16816(acc[mt][nt], af[mt],
                             bf[nt >> 1][(nt & 1) * 2], bf[nt >> 1][(nt & 1) * 2 + 1]);
        }
        // next iteration's leading wait+sync protects this stage before reuse
    }

    // Epilogue: canonical m16n8 C fragment scatter
    float* Cw = C + (size_t)(bm * 128 + warp_m * 64) * N + bn * 128 + warp_n * 32;
    const int tr = lane >> 2, tc = (lane & 3) * 2;
#pragma unroll
    for (int mt = 0; mt < 4; mt++)
#pragma unroll
        for (int nt = 0; nt < 4; nt++) {
            float* p = Cw + (size_t)(mt * 16 + tr) * N + nt * 8 + tc;
            *(float2*)p = make_float2(acc[mt][nt][0], acc[mt][nt][1]);
            *(float2*)(p + (size_t)8 * N) = make_float2(acc[mt][nt][2], acc[mt][nt][3]);
        }
}
#define GEMM_SMEM (4 * STAGE_B)   // 73728 bytes

// ---------------------------------------------------------------------------
// Operand prep: split fp32 into bf16 hi/lo, stacked along K.
// A layout: [hi | lo | hi], B layout: [hi ; hi ; lo]  (A'B' = AhBh+AlBh+AhBl)
// ---------------------------------------------------------------------------
__global__ void transpose_split_kernel(const float* __restrict__ W,
                                       __nv_bfloat16* __restrict__ Bp,
                                       int K, int N)
{
    __shared__ float tile[32][33];
    const int k0 = blockIdx.y * 32, n0 = blockIdx.x * 32;
    const int tx = threadIdx.x, ty = threadIdx.y;   // (32, 8)
#pragma unroll
    for (int i = 0; i < 32; i += 8)
        tile[ty + i][tx] = W[(size_t)(k0 + ty + i) * N + (n0 + tx)];
    __syncthreads();
    const size_t K3 = 3 * (size_t)K;
#pragma unroll
    for (int i = 0; i < 32; i += 8) {
        const int n = n0 + ty + i, k = k0 + tx;
        const float v = tile[tx][ty + i];
        const __nv_bfloat16 hi = __float2bfloat16(v);
        const float lo = v - __bfloat162float(hi);
        __nv_bfloat16* row = Bp + (size_t)n * K3;
        row[k] = hi; row[K + k] = hi; row[2 * K + k] = __float2bfloat16(lo);
    }
}

__global__ void split_a_kernel(const float* __restrict__ X,
                               __nv_bfloat16* __restrict__ Ap,
                               int rows, int K)
{
    const int idx = blockIdx.x * blockDim.x + threadIdx.x;
    if (idx >= rows * K) return;
    const int r = idx / K, k = idx % K;
    const float v = X[idx];
    const __nv_bfloat16 hi = __float2bfloat16(v);
    const float lo = v - __bfloat162float(hi);
    __nv_bfloat16* row = Ap + (size_t)r * (3 * (size_t)K);
    row[k] = hi; row[K + k] = __float2bfloat16(lo); row[2 * K + k] = hi;
}

// ---------------------------------------------------------------------------
// Block reduction (256 threads)
// ---------------------------------------------------------------------------
__device__ __forceinline__ float block_reduce_sum(float v, float* sbuf)
{
#pragma unroll
    for (int o = 16; o > 0; o >>= 1) v += __shfl_down_sync(0xffffffffu, v, o);
    const int lane = threadIdx.x & 31, w = threadIdx.x >> 5;
    if (lane == 0) sbuf[w] = v;
    __syncthreads();
    if (w == 0) {
        v = (lane < 8) ? sbuf[lane] : 0.0f;
#pragma unroll
        for (int o = 16; o > 0; o >>= 1) v += __shfl_down_sync(0xffffffffu, v, o);
        if (lane == 0) sbuf[0] = v;
    }
    __syncthreads();
    v = sbuf[0];
    __syncthreads();
    return v;
}

// ---------------------------------------------------------------------------
// In-place row LayerNorm over width 8192 (LN(x@wx)). 1 CTA / row.
// ---------------------------------------------------------------------------
__global__ __launch_bounds__(256) void ln_rows_kernel(
    float* __restrict__ Z, const float* __restrict__ g, const float* __restrict__ b)
{
    __shared__ float sbuf[32];
    const int tid = threadIdx.x;
    float* row = Z + (size_t)blockIdx.x * G4;

    float v[32];
    float s = 0.0f;
#pragma unroll
    for (int i = 0; i < 32; i++) { v[i] = row[tid + i * 256]; s += v[i]; }
    const float mean = block_reduce_sum(s, sbuf) * (1.0f / G4);
    float sq = 0.0f;
#pragma unroll
    for (int i = 0; i < 32; i++) { float d = v[i] - mean; sq += d * d; }
    const float var = block_reduce_sum(sq, sbuf) * (1.0f / G4);
    const float rstd = rsqrtf(var + LN_EPS);
#pragma unroll
    for (int i = 0; i < 32; i++) {
        const int col = tid + i * 256;
        row[col] = (v[i] - mean) * rstd * g[col] + b[col];
    }
}

// ---------------------------------------------------------------------------
// Per-step fused LSTM pointwise. 1 CTA per batch row.
// Sums the two split-K GEMM partials, then LN/gates/state update.
// Also emits next step's split-A operand (h * keep_{t+1} as bf16 hi/lo/hi).
// ---------------------------------------------------------------------------
__global__ __launch_bounds__(256) void lstm_step_kernel(
    const float* __restrict__ gw0, const float* __restrict__ gw1,
    const float* __restrict__ zx_t,
    const float* __restrict__ mask_t, const float* __restrict__ bias,
    const float* __restrict__ gh, const float* __restrict__ bh,
    const float* __restrict__ gc, const float* __restrict__ bc,
    float* __restrict__ c_st, float* __restrict__ h_st,
    float* __restrict__ hs_out,
    __nv_bfloat16* __restrict__ a_next, const float* __restrict__ mask_next)
{
    __shared__ float zsh[G4];
    __shared__ float sbuf[32];

    const int bb = blockIdx.x, tid = threadIdx.x;
    const float* grow0 = gw0 + (size_t)bb * G4;
    const float* grow1 = gw1 + (size_t)bb * G4;
    const float* zrow = zx_t + (size_t)bb * G4;

    float v[32];
    float s = 0.0f;
#pragma unroll
    for (int i = 0; i < 32; i++) {
        v[i] = grow0[tid + i * 256] + grow1[tid + i * 256];
        s += v[i];
    }
    const float mean = block_reduce_sum(s, sbuf) * (1.0f / G4);
    float sq = 0.0f;
#pragma unroll
    for (int i = 0; i < 32; i++) { float d = v[i] - mean; sq += d * d; }
    const float var = block_reduce_sum(sq, sbuf) * (1.0f / G4);
    const float rstd = rsqrtf(var + LN_EPS);

#pragma unroll
    for (int i = 0; i < 32; i++) {
        const int col = tid + i * 256;
        zsh[col] = zrow[col] + (v[i] - mean) * rstd * gh[col] + bh[col] + bias[col];
    }
    __syncthreads();

    const float keep = 1.0f - mask_t[bb];
    float cv[8], ov[8];
    float s2 = 0.0f;
#pragma unroll
    for (int j = 0; j < 8; j++) {
        const int jj = tid + j * 256;
        const float zi = zsh[jj];
        const float zf = zsh[HDIM + jj];
        const float zo = zsh[2 * HDIM + jj];
        const float zu = zsh[3 * HDIM + jj];
        const float ig = 1.0f / (1.0f + expf(-zi));
        const float fg = 1.0f / (1.0f + expf(-zf));
        const float og = 1.0f / (1.0f + expf(-zo));
        const float ug = tanhf(zu);
        const float cold = c_st[bb * HDIM + jj] * keep;
        const float c = fg * cold + ig * ug;
        cv[j] = c; ov[j] = og; s2 += c;
    }

    const float mean2 = block_reduce_sum(s2, sbuf) * (1.0f / HDIM);
    float sq2 = 0.0f;
#pragma unroll
    for (int j = 0; j < 8; j++) { float d = cv[j] - mean2; sq2 += d * d; }
    const float var2 = block_reduce_sum(sq2, sbuf) * (1.0f / HDIM);
    const float rstd2 = rsqrtf(var2 + LN_EPS);

    const float keep_n = a_next ? (1.0f - mask_next[bb]) : 0.0f;
#pragma unroll
    for (int j = 0; j < 8; j++) {
        const int jj = tid + j * 256;
        const float h = ov[j] * tanhf((cv[j] - mean2) * rstd2 * gc[jj] + bc[jj]);
        c_st[bb * HDIM + jj] = cv[j];
        h_st[bb * HDIM + jj] = h;
        hs_out[(size_t)bb * HDIM + jj] = h;
        if (a_next) {
            const float hk = h * keep_n;
            const __nv_bfloat16 hi = __float2bfloat16(hk);
            const float lo = hk - __bfloat162float(hi);
            __nv_bfloat16* row = a_next + (size_t)bb * KPH;
            row[jj] = hi;
            row[HDIM + jj] = __float2bfloat16(lo);
            row[2 * HDIM + jj] = hi;
        }
    }
}

// ---------------------------------------------------------------------------
// State init (also builds step-0 split-A operand) + final state pack
// ---------------------------------------------------------------------------
__global__ void init_state_kernel(const float* __restrict__ init,
                                  const float* __restrict__ mask0,
                                  float* __restrict__ c_st, float* __restrict__ h_st,
                                  __nv_bfloat16* __restrict__ a0)
{
    const int idx = blockIdx.x * blockDim.x + threadIdx.x;
    if (idx >= BATCH * HDIM) return;
    const int b = idx / HDIM, j = idx % HDIM;
    const size_t base = (size_t)b * T_STEPS * 2 * HDIM;
    const float c0 = init[base + j];
    const float h0 = init[base + HDIM + j];
    c_st[idx] = c0;
    h_st[idx] = h0;
    const float hk = h0 * (1.0f - mask0[b]);
    const __nv_bfloat16 hi = __float2bfloat16(hk);
    const float lo = hk - __bfloat162float(hi);
    __nv_bfloat16* row = a0 + (size_t)b * KPH;
    row[j] = hi;
    row[HDIM + j] = __float2bfloat16(lo);
    row[2 * HDIM + j] = hi;
}

__global__ void write_s_kernel(const float* __restrict__ c_st,
                               const float* __restrict__ h_st,
                               float* __restrict__ s_out)
{
    const int idx = blockIdx.x * blockDim.x + threadIdx.x;
    if (idx >= BATCH * 2 * HDIM) return;
    const int b = idx / (2 * HDIM), j = idx % (2 * HDIM);
    s_out[idx] = (j < HDIM) ? c_st[b * HDIM + j] : h_st[b * HDIM + (j - HDIM)];
}

// ---------------------------------------------------------------------------
// Launch
// ---------------------------------------------------------------------------
extern "C" void kernel_launch(void* const* d_in, const int* in_sizes, int n_in,
                              void* d_out, int out_size)
{
    const float* x    = (const float*)d_in[0];   // (T,B,NIN)
    const float* mask = (const float*)d_in[1];   // (T,B,1)
    const float* init = (const float*)d_in[2];   // (B*T, 2H)
    const float* wx   = (const float*)d_in[3];   // (NIN, 4H)
    const float* wh   = (const float*)d_in[4];   // (H, 4H)
    const float* bias = (const float*)d_in[5];
    const float* gx   = (const float*)d_in[6];
    const float* bxv  = (const float*)d_in[7];
    const float* gh   = (const float*)d_in[8];
    const float* bhv  = (const float*)d_in[9];
    const float* gc   = (const float*)d_in[10];
    const float* bc   = (const float*)d_in[11];

    float* out   = (float*)d_out;
    float* hs    = out;
    float* s_out = out + (size_t)T_STEPS * BATCH * HDIM;

    float *zx, *gw, *c_st, *h_st;
    __nv_bfloat16 *ah, *ax, *bwh, *bwx;
    cudaGetSymbolAddress((void**)&zx,  g_zx);
    cudaGetSymbolAddress((void**)&gw,  g_gw);
    cudaGetSymbolAddress((void**)&c_st, g_c);
    cudaGetSymbolAddress((void**)&h_st, g_h);
    cudaGetSymbolAddress((void**)&ah,  g_ah);
    cudaGetSymbolAddress((void**)&ax,  g_ax);
    cudaGetSymbolAddress((void**)&bwh, g_bwh);
    cudaGetSymbolAddress((void**)&bwx, g_bwx);

    const size_t GW_STRIDE = (size_t)BATCH * G4;

    cudaFuncSetAttribute(mma_gemm_kernel,
                         cudaFuncAttributeMaxDynamicSharedMemorySize, GEMM_SMEM);
    // Force max smem carveout so TWO 73.7KB CTAs co-reside per SM (the driver
    // otherwise picks the smallest config >= per-CTA need -> 1 CTA/SM).
    cudaFuncSetAttribute(mma_gemm_kernel,
                         cudaFuncAttributePreferredSharedMemoryCarveout, 100);

    // Phase 0: operand prep (split fp32 -> stacked bf16)
    transpose_split_kernel<<<dim3(G4 / 32, HDIM / 32), dim3(32, 8)>>>(wh, bwh, HDIM, G4);
    transpose_split_kernel<<<dim3(G4 / 32, NINF / 32), dim3(32, 8)>>>(wx, bwx, NINF, G4);
    split_a_kernel<<<(T_STEPS * BATCH * NINF + 255) / 256, 256>>>(
        x, ax, T_STEPS * BATCH, NINF);

    // Phase 1: zx = X' @ wx'  (16384 x 8192, K'=3072), then in-place LN
    mma_gemm_kernel<<<dim3(G4 / 128, (T_STEPS * BATCH) / 128, 1), 256, GEMM_SMEM>>>(
        ax, bwx, zx, G4, KPX, KPX, 0);
    ln_rows_kernel<<<T_STEPS * BATCH, 256>>>(zx, gx, bxv);

    // State init (+ step-0 A operand)
    init_state_kernel<<<(BATCH * HDIM + 255) / 256, 256>>>(init, mask, c_st, h_st, ah);

    // Sequential scan: split-K=2 recurrent GEMM (256 CTAs, one wave) + pointwise
    for (int t = 0; t < T_STEPS; t++) {
        mma_gemm_kernel<<<dim3(G4 / 128, BATCH / 128, 2), 256, GEMM_SMEM>>>(
            ah, bwh, gw, G4, KPH, KPH / 2, GW_STRIDE);

        const bool last = (t == T_STEPS - 1);
        lstm_step_kernel<<<BATCH, 256>>>(
            gw, gw + GW_STRIDE,
            zx + (size_t)t * BATCH * G4, mask + (size_t)t * BATCH,
            bias, gh, bhv, gc, bc, c_st, h_st,
            hs + (size_t)t * BATCH * HDIM,
            last ? nullptr : ah,
            last ? nullptr : (mask + (size_t)(t + 1) * BATCH));
    }

    write_s_kernel<<<(BATCH * 2 * HDIM + 255) / 256, 256>>>(c_st, h_st, s_out);
}